// round 3
// baseline (speedup 1.0000x reference)
#include <cuda_runtime.h>
#include <cmath>

// ---------------------------------------------------------------------------
// MultiheadChannelAttention on GB300 — Round 1: correct fp32 baseline.
//
// All GEMMs expressed as NT: C[M,N] = alpha * A[M,K] @ B[N,K]^T, row-major.
//   KT[bh][j][n] = sum_k emb_all[b][n][k] * WK[h][j][k]   (A=WK, B=emb_all)
//   V [bh][n][j] = sum_k emb_all[b][n][k] * WV[h][j][k]   (A=emb_all, B=WV)
//   Q [bh][e][n] = sum_d emb[b][n][d]    * WQ[h][e][d]    (A=WQ, B=emb)
//   S [bh][e][j] = scale * sum_n Q[e][n] * KT[j][n]       (A=Q, B=KT)
//   A = softmax_j(S * inv_std)   (instance-norm mean cancels inside softmax)
//   C [bh][e][n] = sum_j A[e][j] * V[n][j]                (A=S, B=V)
//   Cm[b][n][e]  = mean_h C[bh][e][n]                     (transpose+mean)
//   O [b][n][f]  = sum_e Cm[n][e] * WO[f][e]              (A=Cm, B=WO)
// ---------------------------------------------------------------------------

#define BMT 128
#define BNT 128
#define BKT 8

// Scratch (allocation-free rule: __device__ globals)
__device__ float g_KT[32u * 960 * 1024];   // 125.8 MB
__device__ float g_V [32u * 1024 * 960];   // 125.8 MB
__device__ float g_Q [32u * 512 * 1024];   //  67.1 MB (reused per branch)
__device__ float g_S [32u * 512 * 960];    //  62.9 MB (reused per branch)
__device__ float g_C [32u * 512 * 1024];   //  67.1 MB (reused per branch)
__device__ float g_Cm[ 8u * 1024 * 512];   //  16.8 MB (reused per branch)
__device__ float g_invstd[32];

// ---------------------------------------------------------------------------
// Batched NT SGEMM. batch index bh in gridDim.z; b = bh/H, h = bh%H.
// A offset = b*aStrideB + h*aStrideH ; B offset = b*bStrideB + h*bStrideH.
// ---------------------------------------------------------------------------
__global__ __launch_bounds__(256) void gemm_nt(
    const float* __restrict__ Ag, const float* __restrict__ Bg,
    float* __restrict__ Cg,
    int M, int N, int Kin,
    long long aStrideB, long long aStrideH,
    long long bStrideB, long long bStrideH,
    long long cStride, int H, float alpha)
{
    const int tid = threadIdx.x;
    const int tx  = tid & 15;       // 16 x 16 thread grid
    const int ty  = tid >> 4;
    const int bh  = blockIdx.z;
    const int b   = bh / H;
    const int h   = bh - b * H;

    const float* A = Ag + (long long)b * aStrideB + (long long)h * aStrideH;
    const float* B = Bg + (long long)b * bStrideB + (long long)h * bStrideH;
    float*       C = Cg + (long long)bh * cStride;

    __shared__ float As[BKT][BMT];
    __shared__ float Bs[BKT][BNT];

    const int m0 = blockIdx.y * BMT;
    const int n0 = blockIdx.x * BNT;

    float acc[8][8];
#pragma unroll
    for (int i = 0; i < 8; i++)
#pragma unroll
        for (int j = 0; j < 8; j++) acc[i][j] = 0.f;

    const int lrow = tid >> 1;          // 0..127
    const int lcol = (tid & 1) * 4;     // 0 or 4

    for (int k0 = 0; k0 < Kin; k0 += BKT) {
        float4 av = make_float4(0.f, 0.f, 0.f, 0.f);
        float4 bv = make_float4(0.f, 0.f, 0.f, 0.f);
        const int gm = m0 + lrow;
        if (gm < M)
            av = *reinterpret_cast<const float4*>(A + (long long)gm * Kin + (k0 + lcol));
        const int gn = n0 + lrow;
        if (gn < N)
            bv = *reinterpret_cast<const float4*>(B + (long long)gn * Kin + (k0 + lcol));

        As[lcol + 0][lrow] = av.x; As[lcol + 1][lrow] = av.y;
        As[lcol + 2][lrow] = av.z; As[lcol + 3][lrow] = av.w;
        Bs[lcol + 0][lrow] = bv.x; Bs[lcol + 1][lrow] = bv.y;
        Bs[lcol + 2][lrow] = bv.z; Bs[lcol + 3][lrow] = bv.w;
        __syncthreads();

#pragma unroll
        for (int kk = 0; kk < BKT; kk++) {
            const float4 a0 = *reinterpret_cast<const float4*>(&As[kk][ty * 4]);
            const float4 a1 = *reinterpret_cast<const float4*>(&As[kk][64 + ty * 4]);
            const float4 b0 = *reinterpret_cast<const float4*>(&Bs[kk][tx * 4]);
            const float4 b1 = *reinterpret_cast<const float4*>(&Bs[kk][64 + tx * 4]);
            const float ar[8] = {a0.x, a0.y, a0.z, a0.w, a1.x, a1.y, a1.z, a1.w};
            const float br[8] = {b0.x, b0.y, b0.z, b0.w, b1.x, b1.y, b1.z, b1.w};
#pragma unroll
            for (int i = 0; i < 8; i++)
#pragma unroll
                for (int j = 0; j < 8; j++)
                    acc[i][j] = fmaf(ar[i], br[j], acc[i][j]);
        }
        __syncthreads();
    }

#pragma unroll
    for (int i = 0; i < 8; i++) {
        const int gm = m0 + ((i < 4) ? (ty * 4 + i) : (64 + ty * 4 + (i - 4)));
        if (gm >= M) continue;
#pragma unroll
        for (int j = 0; j < 8; j += 4) {
            const int gn = n0 + ((j < 4) ? (tx * 4) : (64 + tx * 4));
            if (gn + 3 < N) {
                float4 o = make_float4(alpha * acc[i][j + 0], alpha * acc[i][j + 1],
                                       alpha * acc[i][j + 2], alpha * acc[i][j + 3]);
                *reinterpret_cast<float4*>(C + (long long)gm * N + gn) = o;
            } else {
#pragma unroll
                for (int jj = 0; jj < 4; jj++)
                    if (gn + jj < N)
                        C[(long long)gm * N + gn + jj] = alpha * acc[i][j + jj];
            }
        }
    }
}

// ---------------------------------------------------------------------------
// Per-(b,h) biased variance over the whole d x KV score map -> inv_std.
// (Mean itself cancels in softmax, only inv_std is needed downstream.)
// ---------------------------------------------------------------------------
__global__ __launch_bounds__(256) void stats_kernel(
    const float* __restrict__ S, float* __restrict__ invstd, int elems)
{
    const int bh = blockIdx.x;
    const float4* p = reinterpret_cast<const float4*>(S + (long long)bh * elems);
    const int n4 = elems >> 2;
    float s = 0.f, s2 = 0.f;
    for (int i = threadIdx.x; i < n4; i += 256) {
        float4 v = p[i];
        s  += v.x + v.y + v.z + v.w;
        s2 += v.x * v.x + v.y * v.y + v.z * v.z + v.w * v.w;
    }
    __shared__ float sh0[256], sh1[256];
    sh0[threadIdx.x] = s; sh1[threadIdx.x] = s2;
    __syncthreads();
    for (int off = 128; off > 0; off >>= 1) {
        if (threadIdx.x < off) {
            sh0[threadIdx.x] += sh0[threadIdx.x + off];
            sh1[threadIdx.x] += sh1[threadIdx.x + off];
        }
        __syncthreads();
    }
    if (threadIdx.x == 0) {
        const float inv = 1.f / (float)elems;
        const float m   = sh0[0] * inv;
        const float var = sh1[0] * inv - m * m;
        invstd[bh] = rsqrtf(var + 1e-5f);
    }
}

// ---------------------------------------------------------------------------
// Row softmax over KV, with inv_std scaling, in place. One block per row.
// ---------------------------------------------------------------------------
__global__ __launch_bounds__(256) void softmax_kernel(
    float* __restrict__ S, const float* __restrict__ invstd, int d, int KV)
{
    const long long row = blockIdx.x;           // bh*d + e
    const int bh = (int)(row / d);
    const float is = invstd[bh];
    float* p = S + row * KV;
    const int tid = threadIdx.x;

    float vals[4];
    int cnt = 0;
    float mx = -1e30f;
    for (int i = tid; i < KV; i += 256) {
        const float v = p[i] * is;
        vals[cnt++] = v;
        mx = fmaxf(mx, v);
    }
    __shared__ float sh[256];
    sh[tid] = mx; __syncthreads();
    for (int off = 128; off > 0; off >>= 1) {
        if (tid < off) sh[tid] = fmaxf(sh[tid], sh[tid + off]);
        __syncthreads();
    }
    mx = sh[0];
    __syncthreads();

    float s = 0.f;
    for (int c = 0; c < cnt; c++) { vals[c] = __expf(vals[c] - mx); s += vals[c]; }
    sh[tid] = s; __syncthreads();
    for (int off = 128; off > 0; off >>= 1) {
        if (tid < off) sh[tid] += sh[tid + off];
        __syncthreads();
    }
    const float rs = 1.f / sh[0];
    cnt = 0;
    for (int i = tid; i < KV; i += 256) p[i] = vals[cnt++] * rs;
}

// ---------------------------------------------------------------------------
// Cm[b][n][e] = 0.25 * sum_h C[(b*4+h)][e][n]  (mean over heads + transpose)
// block (32,8); tiles of 32x32 with padded smem transpose.
// ---------------------------------------------------------------------------
__global__ __launch_bounds__(256) void headmean_kernel(
    const float* __restrict__ C, float* __restrict__ Cm, int d, int N)
{
    __shared__ float tile[32][33];
    const int b  = blockIdx.z;
    const int e0 = blockIdx.y * 32;
    const int n0 = blockIdx.x * 32;
    const int tx = threadIdx.x, ty = threadIdx.y;

    for (int r = ty; r < 32; r += 8) {
        const int e = e0 + r;
        float acc = 0.f;
#pragma unroll
        for (int h = 0; h < 4; h++)
            acc += C[(((long long)(b * 4 + h) * d + e) * N) + n0 + tx];
        tile[r][tx] = 0.25f * acc;
    }
    __syncthreads();
    for (int r = ty; r < 32; r += 8) {
        const int n = n0 + r;
        const int e = e0 + tx;
        Cm[((long long)b * N + n) * d + e] = tile[tx][r];
    }
}

// ---------------------------------------------------------------------------
extern "C" void kernel_launch(void* const* d_in, const int* in_sizes, int n_in,
                              void* d_out, int out_size)
{
    (void)in_sizes; (void)n_in; (void)out_size;
    const float* emb[4]  = {(const float*)d_in[0], (const float*)d_in[1],
                            (const float*)d_in[2], (const float*)d_in[3]};
    const float* emb_all = (const float*)d_in[4];
    const float* WQ[4]   = {(const float*)d_in[5], (const float*)d_in[6],
                            (const float*)d_in[7], (const float*)d_in[8]};
    const float* WK      = (const float*)d_in[9];
    const float* WV      = (const float*)d_in[10];
    const float* WO[4]   = {(const float*)d_in[11], (const float*)d_in[12],
                            (const float*)d_in[13], (const float*)d_in[14]};
    float* out = (float*)d_out;

    float *KT, *Vb, *Q, *S, *Cb, *Cm, *invstd;
    cudaGetSymbolAddress((void**)&KT,     g_KT);
    cudaGetSymbolAddress((void**)&Vb,     g_V);
    cudaGetSymbolAddress((void**)&Q,      g_Q);
    cudaGetSymbolAddress((void**)&S,      g_S);
    cudaGetSymbolAddress((void**)&Cb,     g_C);
    cudaGetSymbolAddress((void**)&Cm,     g_Cm);
    cudaGetSymbolAddress((void**)&invstd, g_invstd);

    const int Bsz = 8, H = 4, Nn = 1024, KV = 960;
    const int df[4] = {64, 128, 256, 512};
    const float scale = 1.0f / sqrtf((float)KV);

    auto grid_of = [](int M, int N, int batches) {
        return dim3((unsigned)((N + BNT - 1) / BNT),
                    (unsigned)((M + BMT - 1) / BMT),
                    (unsigned)batches);
    };

    // KT[bh][j][n]  (M=960, N=1024, K=960), A=WK (h-strided), B=emb_all (b-strided)
    gemm_nt<<<grid_of(KV, Nn, Bsz * H), 256>>>(
        WK, emb_all, KT, KV, Nn, KV,
        0LL, (long long)KV * KV,
        (long long)Nn * KV, 0LL,
        (long long)KV * Nn, H, 1.f);

    // V[bh][n][j]  (M=1024, N=960, K=960), A=emb_all, B=WV
    gemm_nt<<<grid_of(Nn, KV, Bsz * H), 256>>>(
        emb_all, WV, Vb, Nn, KV, KV,
        (long long)Nn * KV, 0LL,
        0LL, (long long)KV * KV,
        (long long)Nn * KV, H, 1.f);

    long long out_off = 0;
    for (int br = 0; br < 4; br++) {
        const int d = df[br];

        // Q[bh][e][n] (M=d, N=1024, K=d), A=WQ, B=emb
        gemm_nt<<<grid_of(d, Nn, Bsz * H), 256>>>(
            WQ[br], emb[br], Q, d, Nn, d,
            0LL, (long long)d * d,
            (long long)Nn * d, 0LL,
            (long long)d * Nn, H, 1.f);

        // S[bh][e][j] (M=d, N=960, K=1024), A=Q, B=KT, alpha=scale
        gemm_nt<<<grid_of(d, KV, Bsz * H), 256>>>(
            Q, KT, S, d, KV, Nn,
            (long long)H * d * Nn, (long long)d * Nn,
            (long long)H * KV * Nn, (long long)KV * Nn,
            (long long)d * KV, H, scale);

        // inv_std per (b,h)
        stats_kernel<<<Bsz * H, 256>>>(S, invstd, d * KV);

        // softmax rows, in place
        softmax_kernel<<<Bsz * H * d, 256>>>(S, invstd, d, KV);

        // C[bh][e][n] (M=d, N=1024, K=960), A=S, B=V
        gemm_nt<<<grid_of(d, Nn, Bsz * H), 256>>>(
            S, Vb, Cb, d, Nn, KV,
            (long long)H * d * KV, (long long)d * KV,
            (long long)H * Nn * KV, (long long)Nn * KV,
            (long long)d * Nn, H, 1.f);

        // Cm[b][n][e] = mean over heads, transposed
        {
            dim3 g((unsigned)(Nn / 32), (unsigned)(d / 32), (unsigned)Bsz);
            dim3 blk(32, 8, 1);
            headmean_kernel<<<g, blk>>>(Cb, Cm, d, Nn);
        }

        // O[b][n][f] (M=1024, N=d, K=d), A=Cm (b-strided), B=WO (shared)
        gemm_nt<<<grid_of(Nn, d, Bsz), 256>>>(
            Cm, WO[br], out + out_off, Nn, d, d,
            (long long)Nn * d, 0LL,
            0LL, 0LL,
            (long long)Nn * d, 1, 1.f);

        out_off += (long long)Bsz * Nn * d;
    }
}

// round 5
// speedup vs baseline: 2.2450x; 2.2450x over previous
#include <cuda_runtime.h>
#include <cuda_bf16.h>
#include <cstdint>
#include <cmath>

// ===========================================================================
// MultiheadChannelAttention — Round 3: warp-level HMMA (mma.sync bf16) with
// bf16x3 split numerics. (tcgen05.ld/st are a-only PTX features and the
// harness compiles via compute_103 base target, so TMEM is unreachable.)
// All GEMMs NT: C[M,N] = alpha * A[M,K] @ B[N,K]^T, operands bf16 (hi,lo)
// pairs; C = Ahi*Bhi + Ahi*Blo + Alo*Bhi accumulated in fp32.
// ===========================================================================

// ------------------------- sizes (elements) --------------------------------
constexpr long long N_EMB1 = 8LL*1024*64;
constexpr long long N_EMB2 = 8LL*1024*128;
constexpr long long N_EMB3 = 8LL*1024*256;
constexpr long long N_EMB4 = 8LL*1024*512;
constexpr long long N_EMBA = 8LL*1024*960;
constexpr long long N_WQ1 = 4LL*64*64;
constexpr long long N_WQ2 = 4LL*128*128;
constexpr long long N_WQ3 = 4LL*256*256;
constexpr long long N_WQ4 = 4LL*512*512;
constexpr long long N_WK  = 4LL*960*960;
constexpr long long N_WV  = 4LL*960*960;
constexpr long long N_WO1 = 64LL*64;
constexpr long long N_WO2 = 128LL*128;
constexpr long long N_WO3 = 256LL*256;
constexpr long long N_WO4 = 512LL*512;
constexpr long long N_KT  = 32LL*960*1024;
constexpr long long N_VV  = 32LL*1024*960;
constexpr long long N_Q   = 32LL*512*1024;
constexpr long long N_A   = 32LL*512*960;
constexpr long long N_CM  = 8LL*1024*512;

// ------------------------- device scratch (hi at [0..n), lo at [n..2n)) ----
__device__ __align__(128) __nv_bfloat16 g_emb1p[2*N_EMB1];
__device__ __align__(128) __nv_bfloat16 g_emb2p[2*N_EMB2];
__device__ __align__(128) __nv_bfloat16 g_emb3p[2*N_EMB3];
__device__ __align__(128) __nv_bfloat16 g_emb4p[2*N_EMB4];
__device__ __align__(128) __nv_bfloat16 g_embap[2*N_EMBA];
__device__ __align__(128) __nv_bfloat16 g_wq1p[2*N_WQ1];
__device__ __align__(128) __nv_bfloat16 g_wq2p[2*N_WQ2];
__device__ __align__(128) __nv_bfloat16 g_wq3p[2*N_WQ3];
__device__ __align__(128) __nv_bfloat16 g_wq4p[2*N_WQ4];
__device__ __align__(128) __nv_bfloat16 g_wkp [2*N_WK];
__device__ __align__(128) __nv_bfloat16 g_wvp [2*N_WV];
__device__ __align__(128) __nv_bfloat16 g_wo1p[2*N_WO1];
__device__ __align__(128) __nv_bfloat16 g_wo2p[2*N_WO2];
__device__ __align__(128) __nv_bfloat16 g_wo3p[2*N_WO3];
__device__ __align__(128) __nv_bfloat16 g_wo4p[2*N_WO4];
__device__ __align__(128) __nv_bfloat16 g_ktp [2*N_KT];
__device__ __align__(128) __nv_bfloat16 g_vp  [2*N_VV];
__device__ __align__(128) __nv_bfloat16 g_qp  [2*N_Q];
__device__ __align__(128) __nv_bfloat16 g_ap  [2*N_A];
__device__ __align__(128) __nv_bfloat16 g_cmp [2*N_CM];
__device__ float g_S[N_A];      // fp32 scores (per-branch reuse)
__device__ float g_C[N_Q];      // fp32 context (per-branch reuse)
__device__ float g_invstd[32];

// ------------------------- helpers -----------------------------------------
__device__ __forceinline__ uint32_t smem_u32(const void* p){
    uint32_t a;
    asm("{ .reg .u64 t; cvta.to.shared.u64 t, %1; cvt.u32.u64 %0, t; }"
        : "=r"(a) : "l"(p));
    return a;
}
__device__ __forceinline__ void ldsm_x4(uint32_t a, uint32_t& r0, uint32_t& r1,
                                        uint32_t& r2, uint32_t& r3){
    asm volatile("ldmatrix.sync.aligned.m8n8.x4.shared.b16 {%0,%1,%2,%3}, [%4];"
                 : "=r"(r0), "=r"(r1), "=r"(r2), "=r"(r3) : "r"(a));
}
__device__ __forceinline__ void mma_bf16(float* c, const uint32_t* a,
                                         uint32_t b0, uint32_t b1){
    asm volatile(
        "mma.sync.aligned.m16n8k16.row.col.f32.bf16.bf16.f32 "
        "{%0,%1,%2,%3}, {%4,%5,%6,%7}, {%8,%9}, {%0,%1,%2,%3};"
        : "+f"(c[0]), "+f"(c[1]), "+f"(c[2]), "+f"(c[3])
        : "r"(a[0]), "r"(a[1]), "r"(a[2]), "r"(a[3]), "r"(b0), "r"(b1));
}

// tile geometry
constexpr int BM = 128, BN = 128, BK = 32;
constexpr int TPAD = 40;                 // bf16 elems per smem row (64B data + 16B pad)
constexpr int MAT_BYTES = 128 * TPAD * 2; // 10240 B per matrix tile
constexpr int STAGE_BYTES = 4 * MAT_BYTES;
constexpr int DYN_SMEM = 2 * STAGE_BYTES; // 81920 B

// ===========================================================================
// bf16x3 batched NT GEMM via mma.sync. z-mode: 0 shared, 1 z/H, 2 z%H, 3 z.
// ===========================================================================
__global__ __launch_bounds__(256, 2)
void gemm_bf16x3(
    const __nv_bfloat16* __restrict__ Ahi, const __nv_bfloat16* __restrict__ Alo,
    const __nv_bfloat16* __restrict__ Bhi, const __nv_bfloat16* __restrict__ Blo,
    float* __restrict__ Cf, __nv_bfloat16* __restrict__ Chi, __nv_bfloat16* __restrict__ Clo,
    int M, int N, int K,
    long long aStride, long long bStride,
    int modeA, int modeB, int H, float alpha)
{
    extern __shared__ char dynsmem[];
    const uint32_t sb = smem_u32(dynsmem);

    const int tid  = threadIdx.x;
    const int wid  = tid >> 5;
    const int lane = tid & 31;
    const int wm   = wid >> 1;            // 0..3 -> m offset 32*wm
    const int wn   = wid & 1;             // 0..1 -> n offset 64*wn

    const int z  = blockIdx.z;
    const int zA = (modeA == 0) ? 0 : (modeA == 1) ? (z / H) : (modeA == 2) ? (z % H) : z;
    const int zB = (modeB == 0) ? 0 : (modeB == 1) ? (z / H) : (modeB == 2) ? (z % H) : z;
    const __nv_bfloat16* pA[2] = { Ahi + (long long)zA * aStride, Alo + (long long)zA * aStride };
    const __nv_bfloat16* pB[2] = { Bhi + (long long)zB * bStride, Blo + (long long)zB * bStride };

    const int m0 = blockIdx.y * BM;
    const int n0 = blockIdx.x * BN;
    const int NC = K >> 5;                // chunks of 32

    // ------- async stage fill: 4 mats x 128 rows x 4 x 16B segs ------------
    auto load_stage = [&](int stage, int kc) {
        const int k0 = kc << 5;
#pragma unroll
        for (int it = 0; it < 8; ++it) {
            const int idx = it * 256 + tid;          // 0..2047
            const int mat = idx >> 9;                // 0..3
            const int rem = idx & 511;
            const int row = rem >> 2;                // 0..127
            const int seg = rem & 3;                 // 16B segment
            int g, lim; const __nv_bfloat16* src;
            if (mat < 2) { g = m0 + row; lim = M; src = pA[mat]; }
            else         { g = n0 + row; lim = N; src = pB[mat - 2]; }
            const int valid = (g < lim);
            const uint32_t dst = sb + (uint32_t)(stage * STAGE_BYTES + mat * MAT_BYTES)
                               + (uint32_t)(row * (TPAD * 2) + seg * 16);
            const char* sp = (const char*)(src + (long long)(valid ? g : 0) * K + k0 + seg * 8);
            const uint32_t sz = valid ? 16u : 0u;
            asm volatile("cp.async.cg.shared.global [%0], [%1], 16, %2;"
                         :: "r"(dst), "l"(sp), "r"(sz));
        }
        asm volatile("cp.async.commit_group;" ::: "memory");
    };

    float acc[2][8][4];
#pragma unroll
    for (int t = 0; t < 2; t++)
#pragma unroll
        for (int n = 0; n < 8; n++)
#pragma unroll
            for (int j = 0; j < 4; j++) acc[t][n][j] = 0.f;

    load_stage(0, 0);
    if (NC > 1) load_stage(1, 1);

    for (int kc = 0; kc < NC; ++kc) {
        if (kc + 2 <= NC) { asm volatile("cp.async.wait_group 1;" ::: "memory"); }
        else              { asm volatile("cp.async.wait_group 0;" ::: "memory"); }
        __syncthreads();

        const int st = kc & 1;
        const uint32_t aHb = sb + (uint32_t)(st * STAGE_BYTES);
        const uint32_t aLb = aHb + MAT_BYTES;
        const uint32_t bHb = aHb + 2 * MAT_BYTES;
        const uint32_t bLb = aHb + 3 * MAT_BYTES;
        const uint32_t lrow = (uint32_t)(lane & 15) * (TPAD * 2);
        const uint32_t lseg = (uint32_t)(lane >> 4) * 16;

#pragma unroll
        for (int kk = 0; kk < 2; ++kk) {
            const uint32_t koff = (uint32_t)kk * 32 + lseg;
            uint32_t aH[2][4], aL[2][4];
#pragma unroll
            for (int t = 0; t < 2; ++t) {
                const uint32_t ro = (uint32_t)(wm * 32 + t * 16) * (TPAD * 2) + lrow + koff;
                ldsm_x4(aHb + ro, aH[t][0], aH[t][1], aH[t][2], aH[t][3]);
                ldsm_x4(aLb + ro, aL[t][0], aL[t][1], aL[t][2], aL[t][3]);
            }
#pragma unroll
            for (int p = 0; p < 4; ++p) {
                const uint32_t ro = (uint32_t)(wn * 64 + p * 16) * (TPAD * 2) + lrow + koff;
                uint32_t h0, h1, h2, h3, l0, l1, l2, l3;
                ldsm_x4(bHb + ro, h0, h1, h2, h3);
                ldsm_x4(bLb + ro, l0, l1, l2, l3);
                // n-tile 2p:   bH={h0,h2}, bL={l0,l2}; n-tile 2p+1: {h1,h3},{l1,l3}
#pragma unroll
                for (int t = 0; t < 2; ++t) {
                    mma_bf16(acc[t][2*p],   aH[t], h0, h2);
                    mma_bf16(acc[t][2*p],   aH[t], l0, l2);
                    mma_bf16(acc[t][2*p],   aL[t], h0, h2);
                    mma_bf16(acc[t][2*p+1], aH[t], h1, h3);
                    mma_bf16(acc[t][2*p+1], aH[t], l1, l3);
                    mma_bf16(acc[t][2*p+1], aL[t], h1, h3);
                }
            }
        }
        __syncthreads();
        if (kc + 2 < NC) load_stage(st, kc + 2);
    }

    // ------- epilogue ------------------------------------------------------
    const int grp  = lane >> 2;
    const int tid4 = lane & 3;
#pragma unroll
    for (int t = 0; t < 2; ++t) {
#pragma unroll
        for (int n = 0; n < 8; ++n) {
            const int gn = n0 + wn * 64 + n * 8 + tid4 * 2;
            if (gn >= N) continue;
#pragma unroll
            for (int half = 0; half < 2; ++half) {
                const int gm = m0 + wm * 32 + t * 16 + grp + half * 8;
                if (gm >= M) continue;
                const float v0 = alpha * acc[t][n][half * 2 + 0];
                const float v1 = alpha * acc[t][n][half * 2 + 1];
                const long long base = (long long)z * M * N + (long long)gm * N + gn;
                if (Cf) {
                    *reinterpret_cast<float2*>(Cf + base) = make_float2(v0, v1);
                } else {
                    __nv_bfloat162 hp = __floats2bfloat162_rn(v0, v1);
                    __nv_bfloat162 lp = __floats2bfloat162_rn(v0 - __bfloat162float(hp.x),
                                                              v1 - __bfloat162float(hp.y));
                    *reinterpret_cast<__nv_bfloat162*>(Chi + base) = hp;
                    *reinterpret_cast<__nv_bfloat162*>(Clo + base) = lp;
                }
            }
        }
    }
}

// ===========================================================================
// split fp32 -> bf16 (hi, lo)
// ===========================================================================
__global__ __launch_bounds__(256) void split_kernel(
    const float* __restrict__ src, __nv_bfloat16* __restrict__ hi,
    __nv_bfloat16* __restrict__ lo, long long n)
{
    long long i = (long long)blockIdx.x * blockDim.x + threadIdx.x;
    const long long stride = (long long)gridDim.x * blockDim.x;
    for (; i < n; i += stride) {
        const float x = src[i];
        const __nv_bfloat16 h = __float2bfloat16(x);
        hi[i] = h;
        lo[i] = __float2bfloat16(x - __bfloat162float(h));
    }
}

// ===========================================================================
// per-(b,h) biased variance over d x KV -> inv_std (mean cancels in softmax)
// ===========================================================================
__global__ __launch_bounds__(256) void stats_kernel(
    const float* __restrict__ S, float* __restrict__ invstd, int elems)
{
    const int bh = blockIdx.x;
    const float4* p = reinterpret_cast<const float4*>(S + (long long)bh * elems);
    const int n4 = elems >> 2;
    float s = 0.f, s2 = 0.f;
    for (int i = threadIdx.x; i < n4; i += 256) {
        float4 v = p[i];
        s  += v.x + v.y + v.z + v.w;
        s2 += v.x * v.x + v.y * v.y + v.z * v.z + v.w * v.w;
    }
    __shared__ float sh0[256], sh1[256];
    sh0[threadIdx.x] = s; sh1[threadIdx.x] = s2;
    __syncthreads();
    for (int off = 128; off > 0; off >>= 1) {
        if (threadIdx.x < off) {
            sh0[threadIdx.x] += sh0[threadIdx.x + off];
            sh1[threadIdx.x] += sh1[threadIdx.x + off];
        }
        __syncthreads();
    }
    if (threadIdx.x == 0) {
        const float inv = 1.f / (float)elems;
        const float m   = sh0[0] * inv;
        const float var = sh1[0] * inv - m * m;
        invstd[bh] = rsqrtf(var + 1e-5f);
    }
}

// ===========================================================================
// row softmax over KV with inv_std scaling; writes bf16 (hi, lo) pair
// ===========================================================================
__global__ __launch_bounds__(256) void softmax_kernel(
    const float* __restrict__ S, const float* __restrict__ invstd,
    __nv_bfloat16* __restrict__ Ahi, __nv_bfloat16* __restrict__ Alo,
    int d, int KV)
{
    const long long row = blockIdx.x;           // bh*d + e
    const int bh = (int)(row / d);
    const float is = invstd[bh];
    const float* p = S + row * KV;
    const long long ob = row * KV;
    const int tid = threadIdx.x;

    float vals[4];
    int cnt = 0;
    float mx = -1e30f;
    for (int i = tid; i < KV; i += 256) {
        const float v = p[i] * is;
        vals[cnt++] = v;
        mx = fmaxf(mx, v);
    }
    __shared__ float sh[256];
    sh[tid] = mx; __syncthreads();
    for (int off = 128; off > 0; off >>= 1) {
        if (tid < off) sh[tid] = fmaxf(sh[tid], sh[tid + off]);
        __syncthreads();
    }
    mx = sh[0];
    __syncthreads();

    float s = 0.f;
    for (int c = 0; c < cnt; c++) { vals[c] = __expf(vals[c] - mx); s += vals[c]; }
    sh[tid] = s; __syncthreads();
    for (int off = 128; off > 0; off >>= 1) {
        if (tid < off) sh[tid] += sh[tid + off];
        __syncthreads();
    }
    const float rs = 1.f / sh[0];
    cnt = 0;
    for (int i = tid; i < KV; i += 256) {
        const float a = vals[cnt++] * rs;
        const __nv_bfloat16 h = __float2bfloat16(a);
        Ahi[ob + i] = h;
        Alo[ob + i] = __float2bfloat16(a - __bfloat162float(h));
    }
}

// ===========================================================================
// Cm[b][n][e] = 0.25 * sum_h C[b*4+h][e][n], written as bf16 (hi, lo)
// ===========================================================================
__global__ __launch_bounds__(256) void headmean_kernel(
    const float* __restrict__ C, __nv_bfloat16* __restrict__ Cmhi,
    __nv_bfloat16* __restrict__ Cmlo, int d, int N)
{
    __shared__ float tile[32][33];
    const int b  = blockIdx.z;
    const int e0 = blockIdx.y * 32;
    const int n0 = blockIdx.x * 32;
    const int tx = threadIdx.x, ty = threadIdx.y;

    for (int r = ty; r < 32; r += 8) {
        const int e = e0 + r;
        float acc = 0.f;
#pragma unroll
        for (int h = 0; h < 4; h++)
            acc += C[(((long long)(b * 4 + h) * d + e) * N) + n0 + tx];
        tile[r][tx] = 0.25f * acc;
    }
    __syncthreads();
    for (int r = ty; r < 32; r += 8) {
        const int n = n0 + r;
        const int e = e0 + tx;
        const float v = tile[tx][r];
        const __nv_bfloat16 h = __float2bfloat16(v);
        const long long idx = ((long long)b * N + n) * d + e;
        Cmhi[idx] = h;
        Cmlo[idx] = __float2bfloat16(v - __bfloat162float(h));
    }
}

// ===========================================================================
extern "C" void kernel_launch(void* const* d_in, const int* in_sizes, int n_in,
                              void* d_out, int out_size)
{
    (void)in_sizes; (void)n_in; (void)out_size;
    const float* emb[4]  = {(const float*)d_in[0], (const float*)d_in[1],
                            (const float*)d_in[2], (const float*)d_in[3]};
    const float* emb_all = (const float*)d_in[4];
    const float* WQ[4]   = {(const float*)d_in[5], (const float*)d_in[6],
                            (const float*)d_in[7], (const float*)d_in[8]};
    const float* WK      = (const float*)d_in[9];
    const float* WV      = (const float*)d_in[10];
    const float* WO[4]   = {(const float*)d_in[11], (const float*)d_in[12],
                            (const float*)d_in[13], (const float*)d_in[14]};
    float* out = (float*)d_out;

    __nv_bfloat16 *embp[4], *embap, *wqp[4], *wkp, *wvp, *wop[4];
    __nv_bfloat16 *ktp, *vp, *qp, *ap, *cmp;
    float *S, *C, *invstd;
    cudaGetSymbolAddress((void**)&embp[0], g_emb1p);
    cudaGetSymbolAddress((void**)&embp[1], g_emb2p);
    cudaGetSymbolAddress((void**)&embp[2], g_emb3p);
    cudaGetSymbolAddress((void**)&embp[3], g_emb4p);
    cudaGetSymbolAddress((void**)&embap,   g_embap);
    cudaGetSymbolAddress((void**)&wqp[0],  g_wq1p);
    cudaGetSymbolAddress((void**)&wqp[1],  g_wq2p);
    cudaGetSymbolAddress((void**)&wqp[2],  g_wq3p);
    cudaGetSymbolAddress((void**)&wqp[3],  g_wq4p);
    cudaGetSymbolAddress((void**)&wkp,     g_wkp);
    cudaGetSymbolAddress((void**)&wvp,     g_wvp);
    cudaGetSymbolAddress((void**)&wop[0],  g_wo1p);
    cudaGetSymbolAddress((void**)&wop[1],  g_wo2p);
    cudaGetSymbolAddress((void**)&wop[2],  g_wo3p);
    cudaGetSymbolAddress((void**)&wop[3],  g_wo4p);
    cudaGetSymbolAddress((void**)&ktp,     g_ktp);
    cudaGetSymbolAddress((void**)&vp,      g_vp);
    cudaGetSymbolAddress((void**)&qp,      g_qp);
    cudaGetSymbolAddress((void**)&ap,      g_ap);
    cudaGetSymbolAddress((void**)&cmp,     g_cmp);
    cudaGetSymbolAddress((void**)&S,       g_S);
    cudaGetSymbolAddress((void**)&C,       g_C);
    cudaGetSymbolAddress((void**)&invstd,  g_invstd);

    cudaFuncSetAttribute(gemm_bf16x3, cudaFuncAttributeMaxDynamicSharedMemorySize, DYN_SMEM);

    const int Bsz = 8, H = 4, Nn = 1024, KV = 960;
    const int df[4] = {64, 128, 256, 512};
    const float scale = 1.0f / sqrtf((float)KV);

    auto split = [](const float* s, __nv_bfloat16* p, long long n) {
        int blocks = (int)(((n + 255) / 256 < 4096) ? (n + 255) / 256 : 4096);
        split_kernel<<<blocks, 256>>>(s, p, p + n, n);
    };
    const long long nEmb[4] = {N_EMB1, N_EMB2, N_EMB3, N_EMB4};
    const long long nWQ[4]  = {N_WQ1, N_WQ2, N_WQ3, N_WQ4};
    const long long nWO[4]  = {N_WO1, N_WO2, N_WO3, N_WO4};
    for (int i = 0; i < 4; i++) split(emb[i], embp[i], nEmb[i]);
    split(emb_all, embap, N_EMBA);
    for (int i = 0; i < 4; i++) split(WQ[i], wqp[i], nWQ[i]);
    split(WK, wkp, N_WK);
    split(WV, wvp, N_WV);
    for (int i = 0; i < 4; i++) split(WO[i], wop[i], nWO[i]);

    auto gemm = [&](const __nv_bfloat16* Ah, long long an,
                    const __nv_bfloat16* Bh, long long bn,
                    float* Cf, __nv_bfloat16* Ch, long long cn,
                    int M, int N, int K, long long aS, long long bS,
                    int mA, int mB, int Hh, int Z, float al) {
        dim3 g((unsigned)((N + 127) / 128), (unsigned)((M + 127) / 128), (unsigned)Z);
        gemm_bf16x3<<<g, 256, DYN_SMEM>>>(Ah, Ah + an, Bh, Bh + bn,
                                          Cf, Ch, Ch ? Ch + cn : nullptr,
                                          M, N, K, aS, bS, mA, mB, Hh, al);
    };

    // KT[bh][j][n]: A=WK (per h), B=emb_all (per b)
    gemm(wkp, N_WK, embap, N_EMBA, nullptr, ktp, N_KT,
         KV, Nn, KV, 960LL*960, 1024LL*960, 2, 1, H, Bsz*H, 1.f);
    // V[bh][n][j]: A=emb_all (per b), B=WV (per h)
    gemm(embap, N_EMBA, wvp, N_WV, nullptr, vp, N_VV,
         Nn, KV, KV, 1024LL*960, 960LL*960, 1, 2, H, Bsz*H, 1.f);

    long long out_off = 0;
    for (int br = 0; br < 4; br++) {
        const int d = df[br];

        // Q[bh][e][n]: A=WQ (per h), B=emb (per b)
        gemm(wqp[br], nWQ[br], embp[br], nEmb[br], nullptr, qp, N_Q,
             d, Nn, d, (long long)d*d, 1024LL*d, 2, 1, H, Bsz*H, 1.f);

        // S[bh][e][j] = scale * Q @ KT^T  (fp32 out)
        gemm(qp, N_Q, ktp, N_KT, S, nullptr, 0,
             d, KV, Nn, (long long)d*1024, 960LL*1024, 3, 3, H, Bsz*H, scale);

        stats_kernel<<<Bsz*H, 256>>>(S, invstd, d * KV);
        softmax_kernel<<<Bsz*H*d, 256>>>(S, invstd, ap, ap + N_A, d, KV);

        // C[bh][e][n] = A @ V^T  (fp32 out)
        gemm(ap, N_A, vp, N_VV, C, nullptr, 0,
             d, Nn, KV, (long long)d*960, 1024LL*960, 3, 3, H, Bsz*H, 1.f);

        {
            dim3 g((unsigned)(Nn / 32), (unsigned)(d / 32), (unsigned)Bsz);
            headmean_kernel<<<g, dim3(32, 8, 1)>>>(C, cmp, cmp + N_CM, d, Nn);
        }

        // O[b][n][f]: A=Cm (per b), B=WO (shared) -> fp32 to d_out
        gemm(cmp, N_CM, wop[br], nWO[br], out + out_off, nullptr, 0,
             Nn, d, d, 1024LL*d, 0LL, 3, 0, 1, Bsz, 1.f);

        out_off += (long long)Bsz * Nn * d;
    }
}